// round 17
// baseline (speedup 1.0000x reference)
#include <cuda_runtime.h>
#include <cuda_fp16.h>
#include <cstdint>

// Problem constants (fixed by the dataset)
#define Nn 50000
#define Ee 800000
#define F0 128    // F_IN
#define F1 512    // F_EMB1
#define F2 128    // F_EMB2
#define F3 1024   // F_HID
#define F4 64     // F_OUT

// ---------------------------------------------------------------------------
// Static device scratch (allocation-free rule: __device__ globals)
// ---------------------------------------------------------------------------
__device__ float  g_deg[Nn];
__device__ int    g_cnt[Nn];
__device__ int    g_rowptr[Nn + 1];
__device__ int    g_fill[Nn];
__device__ int2   g_csr[Ee];                  // {src, norm as bits}
__device__ __half g_aggx[(size_t)Nn * F0];    // agg(x), half (feeds GEMM1)
__device__ __half g_h[(size_t)Nn * F1];       // relu(aggx @ W1 + b1), half
__device__ __half g_t[(size_t)Nn * F2];       // h @ W2, half (feeds agg2)
__device__ __half g_h2[(size_t)Nn * F2];      // relu(agg(t) + b2), half
__device__ __half g_hmid[(size_t)Nn * F3];    // relu(h2 @ W3 + b3), half
// Transposed weights, K-major [N, K], half
__device__ __half g_w1t[(size_t)F1 * F0];
__device__ __half g_w2t[(size_t)F2 * F1];
__device__ __half g_w3t[(size_t)F3 * F2];
__device__ __half g_w4t[(size_t)F4 * F3];

// ---------------------------------------------------------------------------
// Portable PTX helpers (sm_80+ only — toolchain targets compute_103 w/o 'a')
// ---------------------------------------------------------------------------
__device__ __forceinline__ uint32_t smem_u32(const void* p) {
    uint32_t a;
    asm("{ .reg .u64 t; cvta.to.shared.u64 t, %1; cvt.u32.u64 %0, t; }"
        : "=r"(a) : "l"(p));
    return a;
}

#define CP_ASYNC16(dst, src) \
    asm volatile("cp.async.cg.shared.global [%0], [%1], 16;" \
                 :: "r"(dst), "l"(src) : "memory")
#define CP_COMMIT() asm volatile("cp.async.commit_group;" ::: "memory")
#define CP_WAIT(n)  asm volatile("cp.async.wait_group %0;" :: "n"(n) : "memory")

// D += A*B  (m16n8k16, fp16 in, fp32 accumulate)
__device__ __forceinline__ void mma_f16(float* c, const uint32_t* a,
                                        const uint32_t* b) {
    asm volatile(
        "mma.sync.aligned.m16n8k16.row.col.f32.f16.f16.f32 "
        "{%0,%1,%2,%3}, {%4,%5,%6,%7}, {%8,%9}, {%0,%1,%2,%3};"
        : "+f"(c[0]), "+f"(c[1]), "+f"(c[2]), "+f"(c[3])
        : "r"(a[0]), "r"(a[1]), "r"(a[2]), "r"(a[3]), "r"(b[0]), "r"(b[1]));
}

// ---------------------------------------------------------------------------
// Graph preprocessing (validated in R11/R13)
// ---------------------------------------------------------------------------
__global__ void init_kernel() {
    int i = blockIdx.x * blockDim.x + threadIdx.x;
    if (i < Nn) { g_deg[i] = 1.0f; g_cnt[i] = 0; }
}

__global__ void deg_cnt_kernel(const int* __restrict__ dst,
                               const float* __restrict__ w) {
    int e = blockIdx.x * blockDim.x + threadIdx.x;
    if (e < Ee) {
        int d = dst[e];
        atomicAdd(&g_deg[d], w[e]);
        atomicAdd(&g_cnt[d], 1);
    }
}

__global__ void scan_kernel() {
    const int T = 1024;
    const int CHUNK = (Nn + T - 1) / T;
    __shared__ int sums[T];
    int t = threadIdx.x;
    int start = t * CHUNK;
    int s = 0;
    for (int i = 0; i < CHUNK; i++) {
        int idx = start + i;
        if (idx < Nn) s += g_cnt[idx];
    }
    sums[t] = s;
    __syncthreads();
    for (int off = 1; off < T; off <<= 1) {
        int v = (t >= off) ? sums[t - off] : 0;
        __syncthreads();
        sums[t] += v;
        __syncthreads();
    }
    int run = (t == 0) ? 0 : sums[t - 1];
    for (int i = 0; i < CHUNK; i++) {
        int idx = start + i;
        if (idx < Nn) {
            g_rowptr[idx] = run;
            g_fill[idx] = run;
            run += g_cnt[idx];
        }
    }
    if (t == T - 1) g_rowptr[Nn] = run;
}

__global__ void place_kernel(const int* __restrict__ src,
                             const int* __restrict__ dst,
                             const float* __restrict__ w) {
    int e = blockIdx.x * blockDim.x + threadIdx.x;
    if (e < Ee) {
        int s = src[e], d = dst[e];
        float nm = rsqrtf(g_deg[s]) * w[e] * rsqrtf(g_deg[d]);
        int pos = atomicAdd(&g_fill[d], 1);
        g_csr[pos] = make_int2(s, __float_as_int(nm));
    }
}

// Tiled transpose + fp16 convert: W [K,N] fp32 -> Wt [N,K] half.
__global__ void transpose_kernel(const float* __restrict__ W,
                                 __half* __restrict__ Wt, int K, int N) {
    __shared__ float t[32][33];
    int n0 = blockIdx.x * 32, k0 = blockIdx.y * 32;
    t[threadIdx.y][threadIdx.x] = W[(size_t)(k0 + threadIdx.y) * N + n0 + threadIdx.x];
    __syncthreads();
    Wt[(size_t)(n0 + threadIdx.y) * K + k0 + threadIdx.x] =
        __float2half_rn(t[threadIdx.x][threadIdx.y]);
}

// ---------------------------------------------------------------------------
// Aggregation: one warp per destination node, 128 features = 32 lanes x 4.
// fp32 accumulation, half output (always feeds a GEMM).
// FP32IN: layer-1 reads the fp32 input x; layer-2 reads the half buffer t.
// ---------------------------------------------------------------------------
template <bool EPI, bool FP32IN>
__global__ __launch_bounds__(256) void agg_kernel(const void* __restrict__ featv,
                                                  const float* __restrict__ bias,
                                                  __half* __restrict__ out) {
    int gw = (blockIdx.x * blockDim.x + threadIdx.x) >> 5;
    int lane = threadIdx.x & 31;
    if (gw >= Nn) return;

    const float4* ff = (const float4*)featv;   // fp32 path
    const uint2*  fh = (const uint2*)featv;    // half path (4 halves)

    float a0, a1, a2, a3;
    if (FP32IN) {
        float4 v = __ldg(&ff[(size_t)gw * 32 + lane]);
        a0 = v.x; a1 = v.y; a2 = v.z; a3 = v.w;
    } else {
        uint2 v = __ldg(&fh[(size_t)gw * 32 + lane]);
        float2 p0 = __half22float2(*(__half2*)&v.x);
        float2 p1 = __half22float2(*(__half2*)&v.y);
        a0 = p0.x; a1 = p0.y; a2 = p1.x; a3 = p1.y;
    }
    float inv = 1.0f / g_deg[gw];
    a0 *= inv; a1 *= inv; a2 *= inv; a3 *= inv;

    int beg = g_rowptr[gw];
    int end = g_rowptr[gw + 1];
    for (int e = beg; e < end; e++) {
        int2 p = g_csr[e];
        float nm = __int_as_float(p.y);
        float v0, v1, v2, v3;
        if (FP32IN) {
            float4 v = __ldg(&ff[(size_t)p.x * 32 + lane]);
            v0 = v.x; v1 = v.y; v2 = v.z; v3 = v.w;
        } else {
            uint2 v = __ldg(&fh[(size_t)p.x * 32 + lane]);
            float2 p0 = __half22float2(*(__half2*)&v.x);
            float2 p1 = __half22float2(*(__half2*)&v.y);
            v0 = p0.x; v1 = p0.y; v2 = p1.x; v3 = p1.y;
        }
        a0 = fmaf(nm, v0, a0);
        a1 = fmaf(nm, v1, a1);
        a2 = fmaf(nm, v2, a2);
        a3 = fmaf(nm, v3, a3);
    }
    if (EPI) {
        float4 b = __ldg(&((const float4*)bias)[lane]);
        a0 = fmaxf(a0 + b.x, 0.0f);
        a1 = fmaxf(a1 + b.y, 0.0f);
        a2 = fmaxf(a2 + b.z, 0.0f);
        a3 = fmaxf(a3 + b.w, 0.0f);
    }
    uint2 o;
    __half2 h0 = __float22half2_rn(make_float2(a0, a1));
    __half2 h1 = __float22half2_rn(make_float2(a2, a3));
    o.x = *(uint32_t*)&h0;
    o.y = *(uint32_t*)&h1;
    ((uint2*)out)[(size_t)gw * 32 + lane] = o;
}

// ---------------------------------------------------------------------------
// FP16 tensor-core GEMM (portable mma.sync m16n8k16):
//   C[M,N] = A[M,K] @ Bt[N,K]^T  (+bias, relu if EPI)
// A, Bt are half; accumulate fp32; output half (or fp32 if OUTF32).
// CTA tile 128 x BN, BK=32 halves, cp.async double-buffered, 256 threads
// (8 warps, 4x2), warp tile 32 x (BN/2). K%32==0, N%BN==0, BN in {64,128}.
// SMEM rows padded to 40 halves (80B) -> fragment LDS conflict-free.
// ---------------------------------------------------------------------------
template <int BN, bool EPI, bool OUTF32>
__global__ __launch_bounds__(256) void mma_gemm(const __half* __restrict__ A,
                                                const __half* __restrict__ Bt,
                                                const float* __restrict__ bias,
                                                void* __restrict__ Cv,
                                                int M, int N, int K) {
    constexpr int BM = 128, BK = 32, STR = 40;   // halves per padded row
    constexpr int WN = BN / 2;
    constexpr int NT = WN / 8;

    extern __shared__ __half sm_h[];
    __half* As0 = sm_h;                  // [2][BM][STR]
    __half* Bs0 = sm_h + 2 * BM * STR;   // [2][BN][STR]
    const uint32_t smb = smem_u32(sm_h);

    const int tid = threadIdx.x;
    const int lane = tid & 31;
    const int wid = tid >> 5;
    const int bm = blockIdx.y * BM;
    const int bn = blockIdx.x * BN;

    // tile-load coords: row of 32 halves = 64B = 4 x cp.async(16B)
    const int lrow = tid >> 2;   // 0..63
    const int lq = tid & 3;      // 16B slot

    const int m_base = (wid & 3) * 32;
    const int n_base = (wid >> 2) * WN;

    float acc[2][NT][4];
#pragma unroll
    for (int mi = 0; mi < 2; mi++)
#pragma unroll
        for (int ni = 0; ni < NT; ni++)
#pragma unroll
            for (int j = 0; j < 4; j++) acc[mi][ni][j] = 0.0f;

    auto prefetch = [&](int c, int s) {
        const int k0 = c * BK;
        const uint32_t abase = smb + (uint32_t)(s * BM * STR) * 2u;
#pragma unroll
        for (int p = 0; p < 2; p++) {            // A: 128 rows, 64 per pass
            int row = lrow + p * 64;
            int grow = bm + row;
            if (grow > M - 1) grow = M - 1;      // clamp: only pollutes OOB rows
            const __half* src = A + (size_t)grow * K + k0 + lq * 8;
            uint32_t dst = abase + (uint32_t)(row * STR) * 2u + (uint32_t)lq * 16u;
            CP_ASYNC16(dst, src);
        }
        const uint32_t bbase = smb + (uint32_t)((2 * BM + s * BN) * STR) * 2u;
#pragma unroll
        for (int p = 0; p < BN / 64; p++) {      // B: BN rows
            int row = lrow + p * 64;
            const __half* src = Bt + (size_t)(bn + row) * K + k0 + lq * 8;
            uint32_t dst = bbase + (uint32_t)(row * STR) * 2u + (uint32_t)lq * 16u;
            CP_ASYNC16(dst, src);
        }
    };

    const int nk = K / BK;
    prefetch(0, 0);
    CP_COMMIT();

    for (int c = 0; c < nk; c++) {
        const int s = c & 1;
        if (c + 1 < nk) {
            prefetch(c + 1, s ^ 1);
            CP_COMMIT();
            CP_WAIT(1);
        } else {
            CP_WAIT(0);
        }
        __syncthreads();

        const __half* Asm = As0 + s * BM * STR;
        const __half* Bsm = Bs0 + s * BN * STR;
#pragma unroll
        for (int kk = 0; kk < BK / 16; kk++) {   // two k16 steps per chunk
            const int c0 = kk * 16 + 2 * (lane & 3);
            uint32_t af[2][4];
#pragma unroll
            for (int mi = 0; mi < 2; mi++) {
                int r = m_base + mi * 16 + (lane >> 2);
                af[mi][0] = *(const uint32_t*)&Asm[r * STR + c0];
                af[mi][1] = *(const uint32_t*)&Asm[(r + 8) * STR + c0];
                af[mi][2] = *(const uint32_t*)&Asm[r * STR + c0 + 8];
                af[mi][3] = *(const uint32_t*)&Asm[(r + 8) * STR + c0 + 8];
            }
            uint32_t bf[NT][2];
#pragma unroll
            for (int ni = 0; ni < NT; ni++) {
                int n = n_base + ni * 8 + (lane >> 2);
                bf[ni][0] = *(const uint32_t*)&Bsm[n * STR + c0];
                bf[ni][1] = *(const uint32_t*)&Bsm[n * STR + c0 + 8];
            }
#pragma unroll
            for (int mi = 0; mi < 2; mi++)
#pragma unroll
                for (int ni = 0; ni < NT; ni++)
                    mma_f16(acc[mi][ni], af[mi], bf[ni]);
        }
        __syncthreads();
    }

    // Epilogue: c0,c1 -> (row, col..col+1); c2,c3 -> (row+8, ...)
    float* Cf = (float*)Cv;
    __half* Ch = (__half*)Cv;
#pragma unroll
    for (int mi = 0; mi < 2; mi++) {
        int row = bm + m_base + mi * 16 + (lane >> 2);
#pragma unroll
        for (int ni = 0; ni < NT; ni++) {
            int col = bn + n_base + ni * 8 + 2 * (lane & 3);
            float2 bb = make_float2(0.f, 0.f);
            if (EPI) bb = *(const float2*)(bias + col);

            float v0 = acc[mi][ni][0], v1 = acc[mi][ni][1];
            float v2 = acc[mi][ni][2], v3 = acc[mi][ni][3];
            if (EPI) {
                v0 = fmaxf(v0 + bb.x, 0.0f); v1 = fmaxf(v1 + bb.y, 0.0f);
                v2 = fmaxf(v2 + bb.x, 0.0f); v3 = fmaxf(v3 + bb.y, 0.0f);
            }
            if (OUTF32) {
                if (row < M)
                    *(float2*)(Cf + (size_t)row * N + col) = make_float2(v0, v1);
                if (row + 8 < M)
                    *(float2*)(Cf + (size_t)(row + 8) * N + col) = make_float2(v2, v3);
            } else {
                if (row < M) {
                    __half2 h = __float22half2_rn(make_float2(v0, v1));
                    *(uint32_t*)(Ch + (size_t)row * N + col) = *(uint32_t*)&h;
                }
                if (row + 8 < M) {
                    __half2 h = __float22half2_rn(make_float2(v2, v3));
                    *(uint32_t*)(Ch + (size_t)(row + 8) * N + col) = *(uint32_t*)&h;
                }
            }
        }
    }
}

// ---------------------------------------------------------------------------
// Launch
// ---------------------------------------------------------------------------
extern "C" void kernel_launch(void* const* d_in, const int* in_sizes, int n_in,
                              void* d_out, int out_size) {
    const float* x  = (const float*)d_in[0];
    const int*   ei = (const int*)d_in[1];     // [2, E]
    const float* ew = (const float*)d_in[2];
    const float* W1 = (const float*)d_in[3];
    const float* b1 = (const float*)d_in[4];
    const float* W2 = (const float*)d_in[5];
    const float* b2 = (const float*)d_in[6];
    const float* W3 = (const float*)d_in[7];
    const float* b3 = (const float*)d_in[8];
    const float* W4 = (const float*)d_in[9];
    const float* b4 = (const float*)d_in[10];
    float* out = (float*)d_out;

    const int* src = ei;
    const int* dst = ei + Ee;

    __half *p_aggx, *p_h, *p_t, *p_h2, *p_hmid;
    __half *p_w1t, *p_w2t, *p_w3t, *p_w4t;
    cudaGetSymbolAddress((void**)&p_aggx, g_aggx);
    cudaGetSymbolAddress((void**)&p_h,    g_h);
    cudaGetSymbolAddress((void**)&p_t,    g_t);
    cudaGetSymbolAddress((void**)&p_h2,   g_h2);
    cudaGetSymbolAddress((void**)&p_hmid, g_hmid);
    cudaGetSymbolAddress((void**)&p_w1t,  g_w1t);
    cudaGetSymbolAddress((void**)&p_w2t,  g_w2t);
    cudaGetSymbolAddress((void**)&p_w3t,  g_w3t);
    cudaGetSymbolAddress((void**)&p_w4t,  g_w4t);

    // dynamic SMEM: ([2][128] + [2][BN]) x 40 halves
    const int smem128 = (2 * 128 * 40 + 2 * 128 * 40) * 2;  // 40960
    const int smem64  = (2 * 128 * 40 + 2 * 64 * 40) * 2;   // 30720
    cudaFuncSetAttribute(mma_gemm<128, true, false>,
                         cudaFuncAttributeMaxDynamicSharedMemorySize, smem128);
    cudaFuncSetAttribute(mma_gemm<128, false, false>,
                         cudaFuncAttributeMaxDynamicSharedMemorySize, smem128);
    cudaFuncSetAttribute(mma_gemm<64, true, true>,
                         cudaFuncAttributeMaxDynamicSharedMemorySize, smem64);

    const int TB = 256;
    int nblk = (Nn + TB - 1) / TB;
    int eblk = (Ee + TB - 1) / TB;
    int wblk = ((Nn * 32) + TB - 1) / TB;
    int mtiles = (Nn + 127) / 128;   // 391

    // 0) weight transposes (K-major, fp16)
    transpose_kernel<<<dim3(F1 / 32, F0 / 32), dim3(32, 32)>>>(W1, p_w1t, F0, F1);
    transpose_kernel<<<dim3(F2 / 32, F1 / 32), dim3(32, 32)>>>(W2, p_w2t, F1, F2);
    transpose_kernel<<<dim3(F3 / 32, F2 / 32), dim3(32, 32)>>>(W3, p_w3t, F2, F3);
    transpose_kernel<<<dim3(F4 / 32, F3 / 32), dim3(32, 32)>>>(W4, p_w4t, F3, F4);

    // 1) degrees + counts, 2) CSR build
    init_kernel<<<nblk, TB>>>();
    deg_cnt_kernel<<<eblk, TB>>>(dst, ew);
    scan_kernel<<<1, 1024>>>();
    place_kernel<<<eblk, TB>>>(src, dst, ew);

    // 3) layer 1: aggregate x first (linearity), then GEMM + bias + relu
    agg_kernel<false, true><<<wblk, TB>>>(x, nullptr, p_aggx);
    mma_gemm<128, true, false><<<dim3(F1 / 128, mtiles), 256, smem128>>>(
        p_aggx, p_w1t, b1, p_h, Nn, F1, F0);

    // 4) layer 2: transform first (512 -> 128), then aggregate + bias + relu
    mma_gemm<128, false, false><<<dim3(F2 / 128, mtiles), 256, smem128>>>(
        p_h, p_w2t, nullptr, p_t, Nn, F2, F1);
    agg_kernel<true, false><<<wblk, TB>>>(p_t, b2, p_h2);

    // 5) MLP
    mma_gemm<128, true, false><<<dim3(F3 / 128, mtiles), 256, smem128>>>(
        p_h2, p_w3t, b3, p_hmid, Nn, F3, F2);
    mma_gemm<64, true, true><<<dim3(F4 / 64, mtiles), 256, smem64>>>(
        p_hmid, p_w4t, b4, out, Nn, F4, F3);
}